// round 3
// baseline (speedup 1.0000x reference)
#include <cuda_runtime.h>
#include <math.h>

// ---------------- problem constants ----------------
#define BB 8
#define CC 512
#define HH 64
#define WW 64
#define PP 4096          // H*W
#define NHH 8
#define HDD 64

// ---------------- scratch (static device globals; no allocation) ----------------
__device__ float g_box1[BB*64*PP];        // 8 MB
__device__ float g_boxes[BB*4*PP];
__device__ float g_edge1[BB*64*PP];       // 8 MB (GN applied in-place)
__device__ float g_edge[BB*NHH*PP];
__device__ float g_qkv[(size_t)BB*1536*PP];   // 201 MB
__device__ float g_attn[(size_t)BB*NHH*HDD*WW*WW]; // 67 MB
__device__ float g_agg[(size_t)BB*CC*PP];     // 67 MB
__device__ float g_y[(size_t)BB*CC*PP];       // 67 MB
__device__ float g_gnstats[BB*8*2];
__device__ float g_bnstats[CC*2];

// ---------------- helpers ----------------
__device__ __forceinline__ float geluf(float x) {
    return 0.5f * x * (1.0f + erff(x * 0.70710678118654752440f));
}
__device__ __forceinline__ float sigm(float x) {
    return 1.0f / (1.0f + __expf(-x));
}

// ---------------- generic 3x3 conv (SAME pad), implicit GEMM ----------------
// grid.x = B*H (one output row per CTA), grid.y = Cout/64. block = 128.
// Input may come from two concatenated tensors (for the fusion conv).
// ACT: 0 = none, 1 = exact GELU
#define CI_CHUNK 8
template<int ACT>
__global__ __launch_bounds__(128) void conv3x3_k(
    const float* __restrict__ in1, int Cin1,
    const float* __restrict__ in2, int Cin2,
    const float* __restrict__ wgt, const float* __restrict__ bias,
    float* __restrict__ out, int Cout)
{
    const int Cin = Cin1 + Cin2;
    const int bh = blockIdx.x;
    const int b = bh >> 6;
    const int h = bh & 63;
    const int co0 = blockIdx.y * 64;
    const int t = threadIdx.x;
    const int tx = t & 7;    // w group of 8: w = tx*8 .. tx*8+7
    const int ty = t >> 3;   // co group of 4: co = co0 + ty*4 .. +3

    __shared__ float sIn[CI_CHUNK][3][66];
    __shared__ float sW[64][CI_CHUNK * 9];

    float acc[4][8];
#pragma unroll
    for (int a = 0; a < 4; a++)
#pragma unroll
        for (int j = 0; j < 8; j++) acc[a][j] = 0.f;

    for (int cb = 0; cb < Cin; cb += CI_CHUNK) {
        __syncthreads();
        // load input slab: CI_CHUNK channels x 3 rows x 66 cols (zero padded)
        for (int idx = t; idx < CI_CHUNK * 3 * 66; idx += 128) {
            int ci = idx / 198;
            int rem = idx - ci * 198;
            int r = rem / 66;
            int col = rem - r * 66;
            int cg = cb + ci;
            float v = 0.f;
            int gh = h - 1 + r;
            int gw = col - 1;
            if (cg < Cin && (unsigned)gh < 64u && (unsigned)gw < 64u) {
                const float* p = (cg < Cin1)
                    ? (in1 + ((size_t)(b * Cin1 + cg)) * PP)
                    : (in2 + ((size_t)(b * Cin2 + (cg - Cin1))) * PP);
                v = p[gh * 64 + gw];
            }
            sIn[ci][r][col] = v;
        }
        // load weight slab: 64 co x CI_CHUNK ci x 9
        for (int idx = t; idx < 64 * CI_CHUNK * 9; idx += 128) {
            int co = idx / (CI_CHUNK * 9);
            int rem = idx - co * (CI_CHUNK * 9);
            int ci = rem / 9;
            int kk = rem - ci * 9;
            int cg = cb + ci;
            float v = 0.f;
            if (cg < Cin) v = wgt[((size_t)(co0 + co) * Cin + cg) * 9 + kk];
            sW[co][ci * 9 + kk] = v;
        }
        __syncthreads();

#pragma unroll 2
        for (int ci = 0; ci < CI_CHUNK; ci++) {
#pragma unroll
            for (int r = 0; r < 3; r++) {
                float iv[10];
#pragma unroll
                for (int j = 0; j < 10; j++) iv[j] = sIn[ci][r][tx * 8 + j];
#pragma unroll
                for (int cj = 0; cj < 4; cj++) {
                    float w0 = sW[ty * 4 + cj][ci * 9 + r * 3 + 0];
                    float w1 = sW[ty * 4 + cj][ci * 9 + r * 3 + 1];
                    float w2 = sW[ty * 4 + cj][ci * 9 + r * 3 + 2];
#pragma unroll
                    for (int wj = 0; wj < 8; wj++) {
                        acc[cj][wj] = fmaf(w0, iv[wj + 0], acc[cj][wj]);
                        acc[cj][wj] = fmaf(w1, iv[wj + 1], acc[cj][wj]);
                        acc[cj][wj] = fmaf(w2, iv[wj + 2], acc[cj][wj]);
                    }
                }
            }
        }
    }

#pragma unroll
    for (int cj = 0; cj < 4; cj++) {
        int co = co0 + ty * 4 + cj;
        float bv = bias[co];
#pragma unroll
        for (int wj = 0; wj < 8; wj++) {
            float v = acc[cj][wj] + bv;
            if (ACT == 1) v = geluf(v);
            out[(((size_t)b * Cout + co) * 64 + h) * 64 + tx * 8 + wj] = v;
        }
    }
}

// ---------------- small 1x1 conv (Cout small): one CTA per (b, co) x p-tile ----------
// ACT: 0 none, 2 sigmoid
template<int ACT>
__global__ void conv1x1_small_k(
    const float* __restrict__ in, const float* __restrict__ wgt,
    const float* __restrict__ bias, float* __restrict__ out,
    int Cin, int Cout)
{
    int bc = blockIdx.x;
    int b = bc / Cout;
    int co = bc - b * Cout;
    int p = blockIdx.y * 256 + threadIdx.x;
    float acc = bias[co];
    const float* ip = in + (size_t)b * Cin * PP + p;
    const float* wp = wgt + (size_t)co * Cin;
    for (int ci = 0; ci < Cin; ci++)
        acc = fmaf(wp[ci], ip[(size_t)ci * PP], acc);
    if (ACT == 2) acc = sigm(acc);
    out[((size_t)b * Cout + co) * PP + p] = acc;
}

// ---------------- big 1x1 conv = GEMM (qkv) ----------------
// grid.x = B*32 (p tiles of 128), grid.y = Cout/64. block = 128.
__global__ __launch_bounds__(128) void gemm1x1_k(
    const float* __restrict__ in, const float* __restrict__ wgt,
    const float* __restrict__ bias, float* __restrict__ out,
    int Cin, int Cout)
{
    int bp = blockIdx.x;
    int b = bp >> 5;
    int p0 = (bp & 31) * 128;
    int co0 = blockIdx.y * 64;
    int t = threadIdx.x;
    int tx = t & 15;   // p group of 8
    int ty = t >> 4;   // co group of 8

    __shared__ float sW[64][17];
    __shared__ float sB[16][132];

    float acc[8][8];
#pragma unroll
    for (int j = 0; j < 8; j++)
#pragma unroll
        for (int c = 0; c < 8; c++) acc[j][c] = 0.f;

    const float* inb = in + (size_t)b * Cin * PP;

    for (int k0 = 0; k0 < Cin; k0 += 16) {
        __syncthreads();
        for (int idx = t; idx < 1024; idx += 128) {
            int co = idx >> 4, k = idx & 15;
            sW[co][k] = wgt[((size_t)(co0 + co)) * Cin + k0 + k];
        }
        for (int idx = t; idx < 2048; idx += 128) {
            int k = idx >> 7, p = idx & 127;
            sB[k][p] = inb[(size_t)(k0 + k) * PP + p0 + p];
        }
        __syncthreads();
#pragma unroll 4
        for (int k = 0; k < 16; k++) {
            float a[8], bb[8];
#pragma unroll
            for (int j = 0; j < 8; j++) a[j] = sW[ty * 8 + j][k];
            float4 b0 = *(const float4*)&sB[k][tx * 8];
            float4 b1 = *(const float4*)&sB[k][tx * 8 + 4];
            bb[0] = b0.x; bb[1] = b0.y; bb[2] = b0.z; bb[3] = b0.w;
            bb[4] = b1.x; bb[5] = b1.y; bb[6] = b1.z; bb[7] = b1.w;
#pragma unroll
            for (int j = 0; j < 8; j++)
#pragma unroll
                for (int c = 0; c < 8; c++)
                    acc[j][c] = fmaf(a[j], bb[c], acc[j][c]);
        }
    }
#pragma unroll
    for (int j = 0; j < 8; j++) {
        int co = co0 + ty * 8 + j;
        float bv = bias[co];
        float* op = out + ((size_t)b * Cout + co) * PP + p0 + tx * 8;
#pragma unroll
        for (int c = 0; c < 8; c++) op[c] = acc[j][c] + bv;
    }
}

// ---------------- GroupNorm stats (per (b, group of 8 ch)) ----------------
__global__ void gn_stats_k(const float* __restrict__ x, float* __restrict__ stats)
{
    int bg = blockIdx.x;              // b*8 + g
    int b = bg >> 3;
    int g = bg & 7;
    const float* p = x + ((size_t)b * 64 + g * 8) * PP;
    float s = 0.f, s2 = 0.f;
    for (int i = threadIdx.x; i < 8 * PP; i += 256) {
        float v = p[i];
        s += v; s2 += v * v;
    }
    __shared__ float rs[8], rs2[8];
#pragma unroll
    for (int o = 16; o > 0; o >>= 1) {
        s  += __shfl_down_sync(0xffffffffu, s,  o);
        s2 += __shfl_down_sync(0xffffffffu, s2, o);
    }
    int w = threadIdx.x >> 5, l = threadIdx.x & 31;
    if (l == 0) { rs[w] = s; rs2[w] = s2; }
    __syncthreads();
    if (w == 0) {
        s  = (l < 8) ? rs[l]  : 0.f;
        s2 = (l < 8) ? rs2[l] : 0.f;
#pragma unroll
        for (int o = 4; o > 0; o >>= 1) {
            s  += __shfl_down_sync(0xffffffffu, s,  o);
            s2 += __shfl_down_sync(0xffffffffu, s2, o);
        }
        if (l == 0) {
            float m = s / 32768.f;
            stats[bg * 2] = m;
            stats[bg * 2 + 1] = s2 / 32768.f - m * m;
        }
    }
}

// ---------------- GroupNorm apply + GELU (in place) ----------------
__global__ void gn_apply_k(float* __restrict__ x, const float* __restrict__ stats,
                           const float* __restrict__ gamma, const float* __restrict__ beta)
{
    size_t idx = (size_t)blockIdx.x * 256 + threadIdx.x;  // total 8*64*4096
    int c = (int)((idx >> 12) & 63);
    int b = (int)(idx >> 18);
    int bg = b * 8 + (c >> 3);
    float m = stats[bg * 2], v = stats[bg * 2 + 1];
    float xn = (x[idx] - m) * rsqrtf(v + 1e-5f) * gamma[c] + beta[c];
    x[idx] = geluf(xn);
}

// ---------------- attention logits: per (b,h,i) do 64x64x64 GEMM + edge bias ----------
__global__ __launch_bounds__(128) void attn_logits_k(
    const float* __restrict__ qkv, const float* __restrict__ edge,
    float* __restrict__ attn)
{
    int id = blockIdx.x;           // (b*8+h)*64 + i
    int i = id & 63;
    int h = (id >> 6) & 7;
    int b = id >> 9;
    const float* Q = qkv + ((size_t)(b * 1536 + h * 64 + i)) * PP;        // (y,w)
    const float* K = qkv + ((size_t)(b * 1536 + 512 + h * 64 + i)) * PP;  // (y,W')
    __shared__ float sQ[64][65], sK[64][65];
    int t = threadIdx.x;
    for (int idx = t; idx < 4096; idx += 128) {
        int r = idx >> 6, c = idx & 63;
        sQ[r][c] = Q[idx];
        sK[r][c] = K[idx];
    }
    __syncthreads();
    int tx = t & 15, ty = t >> 4;   // w = ty*8+j, W' = tx*4+c
    float acc[8][4];
#pragma unroll
    for (int j = 0; j < 8; j++)
#pragma unroll
        for (int c = 0; c < 4; c++) acc[j][c] = 0.f;

#pragma unroll 8
    for (int y = 0; y < 64; y++) {
        float qv[8], kv[4];
#pragma unroll
        for (int j = 0; j < 8; j++) qv[j] = sQ[y][ty * 8 + j];
#pragma unroll
        for (int c = 0; c < 4; c++) kv[c] = sK[y][tx * 4 + c];
#pragma unroll
        for (int j = 0; j < 8; j++)
#pragma unroll
            for (int c = 0; c < 4; c++)
                acc[j][c] = fmaf(qv[j], kv[c], acc[j][c]);
    }
    float* op = attn + (size_t)id * 4096;
    const float* ep = edge + (size_t)id * 64;
#pragma unroll
    for (int j = 0; j < 8; j++) {
        int w = ty * 8 + j;
        float e = ep[w];
#pragma unroll
        for (int c = 0; c < 4; c++)
            op[w * 64 + tx * 4 + c] = acc[j][c] * 0.125f + e;  // scale = 64^-0.5
    }
}

// ---------------- softmax over i (stride 4096 within a (b,h) block) ----------------
__global__ __launch_bounds__(128) void softmax_i_k(float* __restrict__ attn)
{
    int n = blockIdx.x * 128 + threadIdx.x;  // 64 bh * 4096 ww = 262144
    int bh = n >> 12;
    int ww = n & 4095;
    float* p = attn + (size_t)bh * 262144 + ww;
    float x[64];
    float mx = -1e30f;
#pragma unroll
    for (int i = 0; i < 64; i++) {
        x[i] = p[(size_t)i * 4096];
        mx = fmaxf(mx, x[i]);
    }
    float s = 0.f;
#pragma unroll
    for (int i = 0; i < 64; i++) {
        x[i] = __expf(x[i] - mx);
        s += x[i];
    }
    float inv = 1.f / s;
#pragma unroll
    for (int i = 0; i < 64; i++) p[(size_t)i * 4096] = x[i] * inv;
}

// ---------------- AV: agg[d,w] = sum_W' A[w,W'] * V[d,W'] per (b,h,i) -------------
__global__ __launch_bounds__(128) void attn_av_k(
    const float* __restrict__ qkv, const float* __restrict__ attn,
    float* __restrict__ agg)
{
    int id = blockIdx.x;
    int i = id & 63;
    int h = (id >> 6) & 7;
    int b = id >> 9;
    const float* V = qkv + ((size_t)(b * 1536 + 1024 + h * 64 + i)) * PP;  // (d,W')
    const float* A = attn + (size_t)id * 4096;                            // (w,W')
    __shared__ float sV[64][65], sA[64][65];
    int t = threadIdx.x;
    for (int idx = t; idx < 4096; idx += 128) {
        int r = idx >> 6, c = idx & 63;
        sV[r][c] = V[idx];
        sA[r][c] = A[idx];
    }
    __syncthreads();
    int tx = t & 15, ty = t >> 4;   // d = ty*8+j, w = tx*4+c
    float acc[8][4];
#pragma unroll
    for (int j = 0; j < 8; j++)
#pragma unroll
        for (int c = 0; c < 4; c++) acc[j][c] = 0.f;

#pragma unroll 8
    for (int kk = 0; kk < 64; kk++) {
        float vv[8], av[4];
#pragma unroll
        for (int j = 0; j < 8; j++) vv[j] = sV[ty * 8 + j][kk];
#pragma unroll
        for (int c = 0; c < 4; c++) av[c] = sA[tx * 4 + c][kk];
#pragma unroll
        for (int j = 0; j < 8; j++)
#pragma unroll
            for (int c = 0; c < 4; c++)
                acc[j][c] = fmaf(vv[j], av[c], acc[j][c]);
    }
    float* op = agg + ((size_t)(b * 512 + h * 64 + i)) * PP;
#pragma unroll
    for (int j = 0; j < 8; j++)
#pragma unroll
        for (int c = 0; c < 4; c++)
            op[(ty * 8 + j) * 64 + tx * 4 + c] = acc[j][c];
}

// ---------------- BatchNorm stats (per channel over B,H,W) ----------------
__global__ void bn_stats_k(const float* __restrict__ y, float* __restrict__ stats)
{
    int c = blockIdx.x;
    float s = 0.f, s2 = 0.f;
    for (int n = threadIdx.x; n < 32768; n += 256) {
        int b = n >> 12, p = n & 4095;
        float v = y[((size_t)b * CC + c) * PP + p];
        s += v; s2 += v * v;
    }
    __shared__ float rs[8], rs2[8];
#pragma unroll
    for (int o = 16; o > 0; o >>= 1) {
        s  += __shfl_down_sync(0xffffffffu, s,  o);
        s2 += __shfl_down_sync(0xffffffffu, s2, o);
    }
    int w = threadIdx.x >> 5, l = threadIdx.x & 31;
    if (l == 0) { rs[w] = s; rs2[w] = s2; }
    __syncthreads();
    if (w == 0) {
        s  = (l < 8) ? rs[l]  : 0.f;
        s2 = (l < 8) ? rs2[l] : 0.f;
#pragma unroll
        for (int o = 4; o > 0; o >>= 1) {
            s  += __shfl_down_sync(0xffffffffu, s,  o);
            s2 += __shfl_down_sync(0xffffffffu, s2, o);
        }
        if (l == 0) {
            float m = s / 32768.f;
            stats[c * 2] = m;
            stats[c * 2 + 1] = s2 / 32768.f - m * m;
        }
    }
}

// ---------------- BN apply + SiLU -> output ----------------
__global__ void bn_apply_k(const float* __restrict__ y, const float* __restrict__ stats,
                           const float* __restrict__ g, const float* __restrict__ bt,
                           float* __restrict__ out)
{
    size_t idx = (size_t)blockIdx.x * 256 + threadIdx.x;  // 8*512*4096
    int c = (int)((idx >> 12) & 511);
    float m = stats[c * 2], v = stats[c * 2 + 1];
    float yn = (y[idx] - m) * rsqrtf(v + 1e-5f) * g[c] + bt[c];
    out[idx] = yn * (1.f / (1.f + __expf(-yn)));
}

// ---------------- launch ----------------
extern "C" void kernel_launch(void* const* d_in, const int* in_sizes, int n_in,
                              void* d_out, int out_size)
{
    const float* x       = (const float*)d_in[0];
    const float* box_w1  = (const float*)d_in[1];
    const float* box_b1  = (const float*)d_in[2];
    const float* box_w2  = (const float*)d_in[3];
    const float* box_b2  = (const float*)d_in[4];
    const float* edge_w1 = (const float*)d_in[5];
    const float* edge_b1 = (const float*)d_in[6];
    const float* gn_g    = (const float*)d_in[7];
    const float* gn_b    = (const float*)d_in[8];
    const float* edge_w2 = (const float*)d_in[9];
    const float* edge_b2 = (const float*)d_in[10];
    const float* qkv_w   = (const float*)d_in[11];
    const float* qkv_b   = (const float*)d_in[12];
    const float* fus_w   = (const float*)d_in[13];
    const float* fus_b   = (const float*)d_in[14];
    const float* bn_g    = (const float*)d_in[15];
    const float* bn_b    = (const float*)d_in[16];
    float* out = (float*)d_out;

    float *box1, *boxes, *edge1, *edge, *qkv, *attn, *agg, *y, *gnst, *bnst;
    cudaGetSymbolAddress((void**)&box1,  g_box1);
    cudaGetSymbolAddress((void**)&boxes, g_boxes);
    cudaGetSymbolAddress((void**)&edge1, g_edge1);
    cudaGetSymbolAddress((void**)&edge,  g_edge);
    cudaGetSymbolAddress((void**)&qkv,   g_qkv);
    cudaGetSymbolAddress((void**)&attn,  g_attn);
    cudaGetSymbolAddress((void**)&agg,   g_agg);
    cudaGetSymbolAddress((void**)&y,     g_y);
    cudaGetSymbolAddress((void**)&gnst,  g_gnstats);
    cudaGetSymbolAddress((void**)&bnst,  g_bnstats);

    // box net: conv3x3(512->64)+GELU ; conv1x1(64->4)+sigmoid
    conv3x3_k<1><<<dim3(BB * HH, 1), 128>>>(x, 512, nullptr, 0, box_w1, box_b1, box1, 64);
    conv1x1_small_k<2><<<dim3(BB * 4, 16), 256>>>(box1, box_w2, box_b2, boxes, 64, 4);

    // edge net: conv3x3(4->64) ; GN(8) ; GELU ; conv1x1(64->8)
    conv3x3_k<0><<<dim3(BB * HH, 1), 128>>>(boxes, 4, nullptr, 0, edge_w1, edge_b1, edge1, 64);
    gn_stats_k<<<64, 256>>>(edge1, gnst);
    gn_apply_k<<<8192, 256>>>(edge1, gnst, gn_g, gn_b);
    conv1x1_small_k<0><<<dim3(BB * 8, 16), 256>>>(edge1, edge_w2, edge_b2, edge, 64, 8);

    // qkv 1x1 conv (512 -> 1536)
    gemm1x1_k<<<dim3(BB * 32, 24), 128>>>(x, qkv_w, qkv_b, qkv, 512, 1536);

    // attention
    attn_logits_k<<<4096, 128>>>(qkv, edge, attn);
    softmax_i_k<<<2048, 128>>>(attn);
    attn_av_k<<<4096, 128>>>(qkv, attn, agg);

    // fusion conv3x3(concat(x,agg): 1024 -> 512)
    conv3x3_k<0><<<dim3(BB * HH, 8), 128>>>(x, 512, agg, 512, fus_w, fus_b, y, 512);

    // batchnorm (training stats) + SiLU
    bn_stats_k<<<512, 256>>>(y, bnst);
    bn_apply_k<<<65536, 256>>>(y, bnst, bn_g, bn_b, out);
}